// round 11
// baseline (speedup 1.0000x reference)
#include <cuda_runtime.h>
#include <cstdint>

// ChebyshevEncoder fused kernel v8 for GB300 (sm_103a)
//
// Base = v5 skeleton (best): 4-CTA cluster per row-batch, 1024 thr/CTA,
// thread t=(feat=t>>1, khalf=t&1), 16 weight regs, epilogue(b-1) fused
// row-by-row into compute(b).
//
// v8 delta (the one big change): the per-row warp shfl reduction is
// DEFERRED BY ONE ROW. Row r's (sum,sq) stay in registers; their 5-level
// shfl chain + RED store execute interleaved with row r+1's independent
// cheb/matvec/silu stream (row 7 flushed before the window sync). The
// ~150-cycle serial shfl latency is now covered by real work instead of
// stalling the warp every row.
// Kept from v7 (not implicated in its regression): wide CTA-partial
// butterfly, 32B DSMEM push, pre-duplicated (rstd,off) pairs, packed
// f32x2 epilogue with st.global.cs.

#define TPB          1024
#define NUM_CLUSTERS 32
#define NBLK         (NUM_CLUSTERS * 4)
#define ROWS_ITER    8
#define NBATCH       (4096 / ROWS_ITER)          // 512 row-batches

// smem layout (floats)
#define SMEM_A       0                                 // [8][1024] float4 = 32768
#define SMEM_RED     (SMEM_A + ROWS_ITER * TPB * 4)    // [8 rows][32 warps] float2 = 512
#define SMEM_PAR     (SMEM_RED + 512)                  // [2][8 rows][4 ranks] float2 = 128
#define SMEM_MRS     (SMEM_PAR + 128)                  // 8 x float2 (rstd,rstd) = 16
#define SMEM_MRO     (SMEM_MRS + 16)                   // 8 x float2 (off,off) = 16
#define SMEM_G       (SMEM_MRO + 16)                   // [1024] float4 = 4096
#define SMEM_B       (SMEM_G + TPB * 4)                // [1024] float4 = 4096
#define SMEM_FLOATS  (SMEM_B + TPB * 4)
#define SMEM_BYTES   (SMEM_FLOATS * 4)                 // 166,560 B

typedef unsigned long long ull;

__device__ __forceinline__ ull pack2(float lo, float hi) {
    ull r; asm("mov.b64 %0, {%1, %2};" : "=l"(r) : "f"(lo), "f"(hi)); return r;
}
__device__ __forceinline__ void unpack2(ull v, float& lo, float& hi) {
    asm("mov.b64 {%0, %1}, %2;" : "=f"(lo), "=f"(hi) : "l"(v));
}
__device__ __forceinline__ ull ffma2(ull a, ull b, ull c) {
    ull d; asm("fma.rn.f32x2 %0, %1, %2, %3;" : "=l"(d) : "l"(a), "l"(b), "l"(c)); return d;
}
__device__ __forceinline__ ull fadd2(ull a, ull b) {
    ull d; asm("add.rn.f32x2 %0, %1, %2;" : "=l"(d) : "l"(a), "l"(b)); return d;
}
__device__ __forceinline__ float tanhf_hw(float x) {
    float r; asm("tanh.approx.f32 %0, %1;" : "=f"(r) : "f"(x)); return r;
}
__device__ __forceinline__ uint32_t smem_u32(const void* p) {
    return (uint32_t)__cvta_generic_to_shared(p);
}
__device__ __forceinline__ uint32_t mapa_rank(uint32_t laddr, uint32_t rank) {
    uint32_t raddr;
    asm("mapa.shared::cluster.u32 %0, %1, %2;" : "=r"(raddr) : "r"(laddr), "r"(rank));
    return raddr;
}
__device__ __forceinline__ void st_remote_b64(uint32_t raddr, ull v) {
    asm volatile("st.shared::cluster.b64 [%0], %1;" :: "r"(raddr), "l"(v) : "memory");
}
__device__ __forceinline__ void lds_v2u64(uint32_t addr, ull& a, ull& b) {
    asm("ld.shared.v2.u64 {%0, %1}, [%2];" : "=l"(a), "=l"(b) : "r"(addr));
}
__device__ __forceinline__ void stg_cs_v2u64(void* p, ull a, ull b) {
    asm volatile("st.global.cs.v2.u64 [%0], {%1, %2};" :: "l"(p), "l"(a), "l"(b) : "memory");
}
__device__ __forceinline__ void cluster_sync() {
    asm volatile("barrier.cluster.arrive.aligned;" ::: "memory");
    asm volatile("barrier.cluster.wait.aligned;" ::: "memory");
}

__global__ void __launch_bounds__(TPB, 1) __cluster_dims__(4, 1, 1)
cheb_fused_kernel(const float* __restrict__ x,
                  const float* __restrict__ scale,
                  const float* __restrict__ poly,
                  const float* __restrict__ kern,
                  const float* __restrict__ gamma,
                  const float* __restrict__ beta,
                  float* __restrict__ out)
{
    extern __shared__ float sm[];
    const int tid   = threadIdx.x;
    const int lane  = tid & 31;
    const int wid   = tid >> 5;                   // 0..31
    const int feat  = tid >> 1;                   // feature within head
    const int khalf = tid & 1;                    // which 4 of the 8 k-cols
    uint32_t h;
    asm("mov.u32 %0, %%cluster_ctarank;" : "=r"(h));
    const int cid = blockIdx.x >> 2;

    // ---- one-time preload: folded half-row weights (f32x2 packed) + scale ----
    ull W2[8][2];
    const float sc = scale[feat];
    {
        const float4* kp = (const float4*)kern + ((size_t)h * 512 + feat) * 16 + khalf;
        const float4  pv = ((const float4*)poly)[((size_t)h * 512 + feat) * 2 + khalf];
        #pragma unroll
        for (int m = 0; m < 8; m++) {
            float4 a = kp[m * 2];
            W2[m][0] = pack2(a.x * pv.x, a.y * pv.y);
            W2[m][1] = pack2(a.z * pv.z, a.w * pv.w);
        }
    }
    // gamma/beta slices -> smem (read per row via LDS, keeps regs <= 64)
    ((float4*)(sm + SMEM_G))[tid] = __ldg((const float4*)(gamma + (size_t)h * 4096) + tid);
    ((float4*)(sm + SMEM_B))[tid] = __ldg((const float4*)(beta  + (size_t)h * 4096) + tid);

    cluster_sync();  // peers launched; DSMEM slots safe to target

    int prev_row0 = 0;
    const float invN = 1.0f / 16384.0f;

    const uint32_t gaddr = smem_u32((const float4*)(sm + SMEM_G) + tid);
    const uint32_t baddr = smem_u32((const float4*)(sm + SMEM_B) + tid);

    // prefetch x for first row of first batch
    float xnext = x[(size_t)(cid * ROWS_ITER) * 512 + feat];

    #pragma unroll 1
    for (int it = 0; ; ++it) {
        const int batch = cid + it * NUM_CLUSTERS;
        const bool comp = (batch < NBATCH);
        const int row0 = batch * ROWS_ITER;
        const int p = it & 1;

        float4* ap = (float4*)(sm + SMEM_A) + tid;
        float4* op = (float4*)(out + (size_t)prev_row0 * 16384 + (size_t)h * 4096) + tid;

        float psum = 0.f, psq = 0.f;   // pending stats of previous row

        // ---- fused loop: epilogue(prev batch) + deferred-stats + compute ----
        #pragma unroll 1
        for (int r = 0; r < ROWS_ITER; r++) {
            if (it > 0) {
                const ull mrs = ((const ull*)(sm + SMEM_MRS))[r];   // (rstd,rstd)
                const ull mro = ((const ull*)(sm + SMEM_MRO))[r];   // (off,off)
                ull va0, va1, gv0, gv1, bv0, bv1;
                lds_v2u64(smem_u32(ap), va0, va1);
                lds_v2u64(gaddr, gv0, gv1);
                lds_v2u64(baddr, bv0, bv1);
                const ull o0 = ffma2(ffma2(va0, mrs, mro), gv0, bv0);
                const ull o1 = ffma2(ffma2(va1, mrs, mro), gv1, bv1);
                stg_cs_v2u64(op, o0, o1);
                op += 4096;
            }
            if (comp) {
                // ---- flush deferred stats of row r-1 (independent of below;
                //      its shfl latency hides under this row's compute) ----
                if (r > 0) {
                    float s = psum, q = psq;
                    #pragma unroll
                    for (int o = 16; o > 0; o >>= 1) {
                        s += __shfl_xor_sync(0xffffffffu, s, o);
                        q += __shfl_xor_sync(0xffffffffu, q, o);
                    }
                    if (lane == 0)
                        ((float2*)(sm + SMEM_RED))[(r - 1) * 32 + wid] = make_float2(s, q);
                }

                const float xv = xnext;
                {
                    int nb = batch + NUM_CLUSTERS;
                    int nrow = (r < ROWS_ITER - 1) ? (row0 + r + 1)
                             : ((nb < NBATCH) ? nb * ROWS_ITER : row0);
                    xnext = x[(size_t)nrow * 512 + feat];
                }

                const float xs = xv * sc;
                ull t2[7];
                {
                    const float x2 = xs + xs;
                    float tm2 = 1.0f, tm1 = xs;
                    t2[0] = pack2(xs, xs);
                    #pragma unroll
                    for (int m = 2; m < 8; m++) {
                        const float T = fmaf(x2, tm1, -tm2);
                        tm2 = tm1; tm1 = T;
                        t2[m - 1] = pack2(T, T);
                    }
                }
                ull acc0 = W2[0][0], acc1 = W2[0][1];
                #pragma unroll
                for (int m = 0; m < 7; m++) {
                    acc0 = ffma2(t2[m], W2[m + 1][0], acc0);
                    acc1 = ffma2(t2[m], W2[m + 1][1], acc1);
                }

                // silu via tanh: v = b*(1+tanh(b)), b = a/2
                float a0, a1, a2, a3;
                unpack2(acc0, a0, a1);
                unpack2(acc1, a2, a3);
                const float b0 = 0.5f * a0, b1 = 0.5f * a1;
                const float b2 = 0.5f * a2, b3 = 0.5f * a3;
                const float v0 = fmaf(tanhf_hw(b0), b0, b0);
                const float v1 = fmaf(tanhf_hw(b1), b1, b1);
                const float v2 = fmaf(tanhf_hw(b2), b2, b2);
                const float v3 = fmaf(tanhf_hw(b3), b3, b3);

                psum = (v0 + v1) + (v2 + v3);
                psq  = fmaf(v0, v0, fmaf(v1, v1, fmaf(v2, v2, v3 * v3)));

                *ap = make_float4(v0, v1, v2, v3);   // overwrite own slot (safe)
            }
            ap += TPB;
        }

        if (!comp) break;   // drain window flushed last epilogue; done

        // ---- flush row 7's stats ----
        {
            float s = psum, q = psq;
            #pragma unroll
            for (int o = 16; o > 0; o >>= 1) {
                s += __shfl_xor_sync(0xffffffffu, s, o);
                q += __shfl_xor_sync(0xffffffffu, q, o);
            }
            if (lane == 0)
                ((float2*)(sm + SMEM_RED))[7 * 32 + wid] = make_float2(s, q);
        }
        __syncthreads();    // RED complete

        // ---- wide CTA-partial: warp w reduces row w across 32 warps ----
        if (wid < 8) {
            ull v = ((const ull*)(sm + SMEM_RED))[wid * 32 + lane];  // conflict-free
            #pragma unroll
            for (int o = 16; o > 0; o >>= 1) {
                float s0, q0; unpack2(v, s0, q0);
                s0 += __shfl_xor_sync(0xffffffffu, s0, o);
                q0 += __shfl_xor_sync(0xffffffffu, q0, o);
                v = pack2(s0, q0);
            }
            if (lane == 0) {
                const uint32_t laddr =
                    smem_u32((ull*)(sm + SMEM_PAR) + (p * 32 + wid * 4 + (int)h));
                #pragma unroll
                for (uint32_t dst = 0; dst < 4; dst++)
                    st_remote_b64(mapa_rank(laddr, dst), v);
            }
        }
        cluster_sync();   // release our pushes / acquire peers' (PAR double-buffered)

        // ---- finish: 8 lane0s combine 4 rank totals, emit (rstd, off) ----
        if (wid < 8 && lane == 0) {
            const ull* pr = (const ull*)(sm + SMEM_PAR) + p * 32 + wid * 4;
            const ull t = fadd2(fadd2(pr[0], pr[1]), fadd2(pr[2], pr[3]));
            float s, q;
            unpack2(t, s, q);
            const float mean = s * invN;
            const float var  = fmaf(-mean, mean, q * invN);
            const float rstd = rsqrtf(var + 1e-5f);
            const float off  = -mean * rstd;
            ((ull*)(sm + SMEM_MRS))[wid] = pack2(rstd, rstd);
            ((ull*)(sm + SMEM_MRO))[wid] = pack2(off, off);
        }
        __syncthreads();    // MRS/MRO visible before next window's epilogue

        prev_row0 = row0;
    }
}

extern "C" void kernel_launch(void* const* d_in, const int* in_sizes, int n_in,
                              void* d_out, int out_size)
{
    const float* x     = (const float*)d_in[0];   // [4096, 512]
    const float* scale = (const float*)d_in[1];   // [512]
    const float* poly  = (const float*)d_in[2];   // [4, 512, 8]
    const float* kern  = (const float*)d_in[3];   // [4, 512, 8, 8]
    const float* gamma = (const float*)d_in[4];   // [16384]
    const float* beta  = (const float*)d_in[5];   // [16384]
    float* out = (float*)d_out;                   // [4096, 16384]

    (void)in_sizes; (void)n_in; (void)out_size;

    cudaFuncSetAttribute(cheb_fused_kernel,
                         cudaFuncAttributeMaxDynamicSharedMemorySize, SMEM_BYTES);

    cheb_fused_kernel<<<NBLK, TPB, SMEM_BYTES, 0>>>(x, scale, poly, kern, gamma, beta, out);
}

// round 12
// speedup vs baseline: 1.2470x; 1.2470x over previous
#include <cuda_runtime.h>
#include <cstdint>

// ChebyshevEncoder fused kernel v9 for GB300 (sm_103a)
//
// Base = v5 skeleton (best): 4-CTA cluster per row-batch, 1024 thr/CTA,
// thread t=(feat=t>>1, khalf=t&1), 16 weight regs, epilogue(b-1) fused
// row-by-row into compute(b), PLAIN in-loop scalar shfl reduction
// (v4/v6/v7/v8 all proved alternatives worse).
//
// v9 deltas (register/smem-traffic rebalance):
//  - Chebyshev recurrence fused INTO the matvec loop: T_m computed, packed,
//    consumed, discarded. Frees ~10 regs (t2[7] pair array gone).
//  - gamma/beta now live in 4 packed f32x2 REGISTERS (loaded once): kills
//    the 32KB/row/CTA smem reload in the epilogue (L1 was 55% utilized).
//  - kept from v7: wide CTA-partial butterfly + 32B DSMEM push,
//    pre-duplicated (rstd,rstd)/(off,off), packed f32x2 epilogue with
//    st.global.cs.v2.u64.

#define TPB          1024
#define NUM_CLUSTERS 32
#define NBLK         (NUM_CLUSTERS * 4)
#define ROWS_ITER    8
#define NBATCH       (4096 / ROWS_ITER)          // 512 row-batches

// smem layout (floats)
#define SMEM_A       0                                 // [8][1024] float4 = 32768
#define SMEM_RED     (SMEM_A + ROWS_ITER * TPB * 4)    // [8 rows][32 warps] float2 = 512
#define SMEM_PAR     (SMEM_RED + 512)                  // [2][8 rows][4 ranks] float2 = 128
#define SMEM_MRS     (SMEM_PAR + 128)                  // 8 x float2 (rstd,rstd) = 16
#define SMEM_MRO     (SMEM_MRS + 16)                   // 8 x float2 (off,off) = 16
#define SMEM_FLOATS  (SMEM_MRO + 16)
#define SMEM_BYTES   (SMEM_FLOATS * 4)                 // 134,176 B

typedef unsigned long long ull;

__device__ __forceinline__ ull pack2(float lo, float hi) {
    ull r; asm("mov.b64 %0, {%1, %2};" : "=l"(r) : "f"(lo), "f"(hi)); return r;
}
__device__ __forceinline__ void unpack2(ull v, float& lo, float& hi) {
    asm("mov.b64 {%0, %1}, %2;" : "=f"(lo), "=f"(hi) : "l"(v));
}
__device__ __forceinline__ ull ffma2(ull a, ull b, ull c) {
    ull d; asm("fma.rn.f32x2 %0, %1, %2, %3;" : "=l"(d) : "l"(a), "l"(b), "l"(c)); return d;
}
__device__ __forceinline__ ull fadd2(ull a, ull b) {
    ull d; asm("add.rn.f32x2 %0, %1, %2;" : "=l"(d) : "l"(a), "l"(b)); return d;
}
__device__ __forceinline__ float tanhf_hw(float x) {
    float r; asm("tanh.approx.f32 %0, %1;" : "=f"(r) : "f"(x)); return r;
}
__device__ __forceinline__ uint32_t smem_u32(const void* p) {
    return (uint32_t)__cvta_generic_to_shared(p);
}
__device__ __forceinline__ uint32_t mapa_rank(uint32_t laddr, uint32_t rank) {
    uint32_t raddr;
    asm("mapa.shared::cluster.u32 %0, %1, %2;" : "=r"(raddr) : "r"(laddr), "r"(rank));
    return raddr;
}
__device__ __forceinline__ void st_remote_b64(uint32_t raddr, ull v) {
    asm volatile("st.shared::cluster.b64 [%0], %1;" :: "r"(raddr), "l"(v) : "memory");
}
__device__ __forceinline__ void lds_v2u64(uint32_t addr, ull& a, ull& b) {
    asm("ld.shared.v2.u64 {%0, %1}, [%2];" : "=l"(a), "=l"(b) : "r"(addr));
}
__device__ __forceinline__ void stg_cs_v2u64(void* p, ull a, ull b) {
    asm volatile("st.global.cs.v2.u64 [%0], {%1, %2};" :: "l"(p), "l"(a), "l"(b) : "memory");
}
__device__ __forceinline__ void cluster_sync() {
    asm volatile("barrier.cluster.arrive.aligned;" ::: "memory");
    asm volatile("barrier.cluster.wait.aligned;" ::: "memory");
}

__global__ void __launch_bounds__(TPB, 1) __cluster_dims__(4, 1, 1)
cheb_fused_kernel(const float* __restrict__ x,
                  const float* __restrict__ scale,
                  const float* __restrict__ poly,
                  const float* __restrict__ kern,
                  const float* __restrict__ gamma,
                  const float* __restrict__ beta,
                  float* __restrict__ out)
{
    extern __shared__ float sm[];
    const int tid   = threadIdx.x;
    const int lane  = tid & 31;
    const int wid   = tid >> 5;                   // 0..31
    const int feat  = tid >> 1;                   // feature within head
    const int khalf = tid & 1;                    // which 4 of the 8 k-cols
    uint32_t h;
    asm("mov.u32 %0, %%cluster_ctarank;" : "=r"(h));
    const int cid = blockIdx.x >> 2;

    // ---- one-time preload: folded half-row weights (f32x2 packed) + scale ----
    ull W2[8][2];
    const float sc = scale[feat];
    {
        const float4* kp = (const float4*)kern + ((size_t)h * 512 + feat) * 16 + khalf;
        const float4  pv = ((const float4*)poly)[((size_t)h * 512 + feat) * 2 + khalf];
        #pragma unroll
        for (int m = 0; m < 8; m++) {
            float4 a = kp[m * 2];
            W2[m][0] = pack2(a.x * pv.x, a.y * pv.y);
            W2[m][1] = pack2(a.z * pv.z, a.w * pv.w);
        }
    }
    // gamma/beta -> 4 packed f32x2 registers (freed by fused-cheb reg savings)
    ull gv0, gv1, bv0, bv1;
    {
        const float4 gq = __ldg((const float4*)(gamma + (size_t)h * 4096) + tid);
        const float4 bq = __ldg((const float4*)(beta  + (size_t)h * 4096) + tid);
        gv0 = pack2(gq.x, gq.y);  gv1 = pack2(gq.z, gq.w);
        bv0 = pack2(bq.x, bq.y);  bv1 = pack2(bq.z, bq.w);
    }

    cluster_sync();  // peers launched; DSMEM slots safe to target

    int prev_row0 = 0;
    const float invN = 1.0f / 16384.0f;

    // prefetch x for first row of first batch
    float xnext = x[(size_t)(cid * ROWS_ITER) * 512 + feat];

    #pragma unroll 1
    for (int it = 0; ; ++it) {
        const int batch = cid + it * NUM_CLUSTERS;
        const bool comp = (batch < NBATCH);
        const int row0 = batch * ROWS_ITER;
        const int p = it & 1;

        float4* ap = (float4*)(sm + SMEM_A) + tid;
        float4* op = (float4*)(out + (size_t)prev_row0 * 16384 + (size_t)h * 4096) + tid;

        // ---- fused loop: epilogue(prev batch) + compute(this batch) ----
        #pragma unroll 1
        for (int r = 0; r < ROWS_ITER; r++) {
            if (it > 0) {
                const ull mrs = ((const ull*)(sm + SMEM_MRS))[r];   // (rstd,rstd)
                const ull mro = ((const ull*)(sm + SMEM_MRO))[r];   // (off,off)
                ull va0, va1;
                lds_v2u64(smem_u32(ap), va0, va1);
                const ull o0 = ffma2(ffma2(va0, mrs, mro), gv0, bv0);
                const ull o1 = ffma2(ffma2(va1, mrs, mro), gv1, bv1);
                stg_cs_v2u64(op, o0, o1);
                op += 4096;
            }
            if (comp) {
                const float xv = xnext;
                {
                    int nb = batch + NUM_CLUSTERS;
                    int nrow = (r < ROWS_ITER - 1) ? (row0 + r + 1)
                             : ((nb < NBATCH) ? nb * ROWS_ITER : row0);
                    xnext = x[(size_t)nrow * 512 + feat];
                }

                const float xs = xv * sc;
                // matvec with Chebyshev fused in (T computed, packed, consumed)
                ull acc0 = W2[0][0], acc1 = W2[0][1];   // T0 == 1
                {
                    ull tp = pack2(xs, xs);             // T1
                    acc0 = ffma2(tp, W2[1][0], acc0);
                    acc1 = ffma2(tp, W2[1][1], acc1);
                    const float x2 = xs + xs;
                    float tm2 = 1.0f, tm1 = xs;
                    #pragma unroll
                    for (int m = 2; m < 8; m++) {
                        const float T = fmaf(x2, tm1, -tm2);
                        tm2 = tm1; tm1 = T;
                        tp = pack2(T, T);
                        acc0 = ffma2(tp, W2[m][0], acc0);
                        acc1 = ffma2(tp, W2[m][1], acc1);
                    }
                }

                // silu via tanh: v = b*(1+tanh(b)), b = a/2
                float a0, a1, a2, a3;
                unpack2(acc0, a0, a1);
                unpack2(acc1, a2, a3);
                const float b0 = 0.5f * a0, b1 = 0.5f * a1;
                const float b2 = 0.5f * a2, b3 = 0.5f * a3;
                const float v0 = fmaf(tanhf_hw(b0), b0, b0);
                const float v1 = fmaf(tanhf_hw(b1), b1, b1);
                const float v2 = fmaf(tanhf_hw(b2), b2, b2);
                const float v3 = fmaf(tanhf_hw(b3), b3, b3);

                float sum = (v0 + v1) + (v2 + v3);
                float sq  = fmaf(v0, v0, fmaf(v1, v1, fmaf(v2, v2, v3 * v3)));

                *ap = make_float4(v0, v1, v2, v3);   // overwrite own slot (safe)

                // in-loop scalar warp reduction (proven best across v4-v8)
                #pragma unroll
                for (int o = 16; o > 0; o >>= 1) {
                    sum += __shfl_xor_sync(0xffffffffu, sum, o);
                    sq  += __shfl_xor_sync(0xffffffffu, sq,  o);
                }
                if (lane == 0)
                    ((float2*)(sm + SMEM_RED))[r * 32 + wid] = make_float2(sum, sq);
            }
            ap += TPB;
        }

        if (!comp) break;   // drain window flushed last epilogue; done
        __syncthreads();    // RED complete

        // ---- wide CTA-partial: warp w reduces row w across 32 warps ----
        if (wid < 8) {
            ull v = ((const ull*)(sm + SMEM_RED))[wid * 32 + lane];  // conflict-free
            float s0, q0;
            unpack2(v, s0, q0);
            #pragma unroll
            for (int o = 16; o > 0; o >>= 1) {
                s0 += __shfl_xor_sync(0xffffffffu, s0, o);
                q0 += __shfl_xor_sync(0xffffffffu, q0, o);
            }
            if (lane == 0) {
                const uint32_t laddr =
                    smem_u32((ull*)(sm + SMEM_PAR) + (p * 32 + wid * 4 + (int)h));
                const ull t = pack2(s0, q0);
                #pragma unroll
                for (uint32_t dst = 0; dst < 4; dst++)
                    st_remote_b64(mapa_rank(laddr, dst), t);
            }
        }
        cluster_sync();   // release our pushes / acquire peers' (PAR double-buffered)

        // ---- finish: 8 lane0s combine 4 rank totals, emit (rstd, off) ----
        if (wid < 8 && lane == 0) {
            const ull* pr = (const ull*)(sm + SMEM_PAR) + p * 32 + wid * 4;
            const ull t = fadd2(fadd2(pr[0], pr[1]), fadd2(pr[2], pr[3]));
            float s, q;
            unpack2(t, s, q);
            const float mean = s * invN;
            const float var  = fmaf(-mean, mean, q * invN);
            const float rstd = rsqrtf(var + 1e-5f);
            const float off  = -mean * rstd;
            ((ull*)(sm + SMEM_MRS))[wid] = pack2(rstd, rstd);
            ((ull*)(sm + SMEM_MRO))[wid] = pack2(off, off);
        }
        __syncthreads();    // MRS/MRO visible before next window's epilogue

        prev_row0 = row0;
    }
}

extern "C" void kernel_launch(void* const* d_in, const int* in_sizes, int n_in,
                              void* d_out, int out_size)
{
    const float* x     = (const float*)d_in[0];   // [4096, 512]
    const float* scale = (const float*)d_in[1];   // [512]
    const float* poly  = (const float*)d_in[2];   // [4, 512, 8]
    const float* kern  = (const float*)d_in[3];   // [4, 512, 8, 8]
    const float* gamma = (const float*)d_in[4];   // [16384]
    const float* beta  = (const float*)d_in[5];   // [16384]
    float* out = (float*)d_out;                   // [4096, 16384]

    (void)in_sizes; (void)n_in; (void)out_size;

    cudaFuncSetAttribute(cheb_fused_kernel,
                         cudaFuncAttributeMaxDynamicSharedMemorySize, SMEM_BYTES);

    cheb_fused_kernel<<<NBLK, TPB, SMEM_BYTES, 0>>>(x, scale, poly, kern, gamma, beta, out);
}

// round 13
// speedup vs baseline: 1.3842x; 1.1100x over previous
#include <cuda_runtime.h>
#include <cstdint>

// ChebyshevEncoder fused kernel v10 for GB300 (sm_103a)
//
// Base = v9 (best, 100.4us): 4-CTA cluster per row-batch, 1024 thr/CTA,
// thread t=(feat=t>>1, khalf=t&1), 16 weight regs, cheb fused into matvec,
// gamma/beta in packed registers, epilogue(b-1) fused into compute(b),
// wide CTA-partial phase + 32B DSMEM push + pre-duplicated (rstd,off).
//
// v10 delta: the in-loop warp reduction is TRUNCATED at 2 butterfly levels
// (groups of 4 lanes); lanes 0 mod 4 store 8 partials/warp to RED. The
// remaining 3 levels move into the already-existing wide CTA-partial
// phase (warp w reduces row w: 8 conflict-free LDS.64 + 7 add.f32x2 +
// 5-level shfl). Phase structure unchanged; -12 slots and -~78 serial
// cycles per row in the hot loop.

#define TPB          1024
#define NUM_CLUSTERS 32
#define NBLK         (NUM_CLUSTERS * 4)
#define ROWS_ITER    8
#define NBATCH       (4096 / ROWS_ITER)          // 512 row-batches

// smem layout (floats)
#define SMEM_A       0                                 // [8][1024] float4 = 32768
#define SMEM_RED     (SMEM_A + ROWS_ITER * TPB * 4)    // [8 rows][256] float2 = 4096
#define SMEM_PAR     (SMEM_RED + 4096)                 // [2][8 rows][4 ranks] float2 = 128
#define SMEM_MRS     (SMEM_PAR + 128)                  // 8 x float2 (rstd,rstd) = 16
#define SMEM_MRO     (SMEM_MRS + 16)                   // 8 x float2 (off,off) = 16
#define SMEM_FLOATS  (SMEM_MRO + 16)
#define SMEM_BYTES   (SMEM_FLOATS * 4)                 // 148,096 B

typedef unsigned long long ull;

__device__ __forceinline__ ull pack2(float lo, float hi) {
    ull r; asm("mov.b64 %0, {%1, %2};" : "=l"(r) : "f"(lo), "f"(hi)); return r;
}
__device__ __forceinline__ void unpack2(ull v, float& lo, float& hi) {
    asm("mov.b64 {%0, %1}, %2;" : "=f"(lo), "=f"(hi) : "l"(v));
}
__device__ __forceinline__ ull ffma2(ull a, ull b, ull c) {
    ull d; asm("fma.rn.f32x2 %0, %1, %2, %3;" : "=l"(d) : "l"(a), "l"(b), "l"(c)); return d;
}
__device__ __forceinline__ ull fadd2(ull a, ull b) {
    ull d; asm("add.rn.f32x2 %0, %1, %2;" : "=l"(d) : "l"(a), "l"(b)); return d;
}
__device__ __forceinline__ float tanhf_hw(float x) {
    float r; asm("tanh.approx.f32 %0, %1;" : "=f"(r) : "f"(x)); return r;
}
__device__ __forceinline__ uint32_t smem_u32(const void* p) {
    return (uint32_t)__cvta_generic_to_shared(p);
}
__device__ __forceinline__ uint32_t mapa_rank(uint32_t laddr, uint32_t rank) {
    uint32_t raddr;
    asm("mapa.shared::cluster.u32 %0, %1, %2;" : "=r"(raddr) : "r"(laddr), "r"(rank));
    return raddr;
}
__device__ __forceinline__ void st_remote_b64(uint32_t raddr, ull v) {
    asm volatile("st.shared::cluster.b64 [%0], %1;" :: "r"(raddr), "l"(v) : "memory");
}
__device__ __forceinline__ void lds_v2u64(uint32_t addr, ull& a, ull& b) {
    asm("ld.shared.v2.u64 {%0, %1}, [%2];" : "=l"(a), "=l"(b) : "r"(addr));
}
__device__ __forceinline__ void stg_cs_v2u64(void* p, ull a, ull b) {
    asm volatile("st.global.cs.v2.u64 [%0], {%1, %2};" :: "l"(p), "l"(a), "l"(b) : "memory");
}
__device__ __forceinline__ void cluster_sync() {
    asm volatile("barrier.cluster.arrive.aligned;" ::: "memory");
    asm volatile("barrier.cluster.wait.aligned;" ::: "memory");
}

__global__ void __launch_bounds__(TPB, 1) __cluster_dims__(4, 1, 1)
cheb_fused_kernel(const float* __restrict__ x,
                  const float* __restrict__ scale,
                  const float* __restrict__ poly,
                  const float* __restrict__ kern,
                  const float* __restrict__ gamma,
                  const float* __restrict__ beta,
                  float* __restrict__ out)
{
    extern __shared__ float sm[];
    const int tid   = threadIdx.x;
    const int lane  = tid & 31;
    const int wid   = tid >> 5;                   // 0..31
    const int feat  = tid >> 1;                   // feature within head
    const int khalf = tid & 1;                    // which 4 of the 8 k-cols
    uint32_t h;
    asm("mov.u32 %0, %%cluster_ctarank;" : "=r"(h));
    const int cid = blockIdx.x >> 2;

    // ---- one-time preload: folded half-row weights (f32x2 packed) + scale ----
    ull W2[8][2];
    const float sc = scale[feat];
    {
        const float4* kp = (const float4*)kern + ((size_t)h * 512 + feat) * 16 + khalf;
        const float4  pv = ((const float4*)poly)[((size_t)h * 512 + feat) * 2 + khalf];
        #pragma unroll
        for (int m = 0; m < 8; m++) {
            float4 a = kp[m * 2];
            W2[m][0] = pack2(a.x * pv.x, a.y * pv.y);
            W2[m][1] = pack2(a.z * pv.z, a.w * pv.w);
        }
    }
    // gamma/beta -> 4 packed f32x2 registers
    ull gv0, gv1, bv0, bv1;
    {
        const float4 gq = __ldg((const float4*)(gamma + (size_t)h * 4096) + tid);
        const float4 bq = __ldg((const float4*)(beta  + (size_t)h * 4096) + tid);
        gv0 = pack2(gq.x, gq.y);  gv1 = pack2(gq.z, gq.w);
        bv0 = pack2(bq.x, bq.y);  bv1 = pack2(bq.z, bq.w);
    }

    cluster_sync();  // peers launched; DSMEM slots safe to target

    int prev_row0 = 0;
    const float invN = 1.0f / 16384.0f;

    // prefetch x for first row of first batch
    float xnext = x[(size_t)(cid * ROWS_ITER) * 512 + feat];

    #pragma unroll 1
    for (int it = 0; ; ++it) {
        const int batch = cid + it * NUM_CLUSTERS;
        const bool comp = (batch < NBATCH);
        const int row0 = batch * ROWS_ITER;
        const int p = it & 1;

        float4* ap = (float4*)(sm + SMEM_A) + tid;
        float4* op = (float4*)(out + (size_t)prev_row0 * 16384 + (size_t)h * 4096) + tid;

        // ---- fused loop: epilogue(prev batch) + compute(this batch) ----
        #pragma unroll 1
        for (int r = 0; r < ROWS_ITER; r++) {
            if (it > 0) {
                const ull mrs = ((const ull*)(sm + SMEM_MRS))[r];   // (rstd,rstd)
                const ull mro = ((const ull*)(sm + SMEM_MRO))[r];   // (off,off)
                ull va0, va1;
                lds_v2u64(smem_u32(ap), va0, va1);
                const ull o0 = ffma2(ffma2(va0, mrs, mro), gv0, bv0);
                const ull o1 = ffma2(ffma2(va1, mrs, mro), gv1, bv1);
                stg_cs_v2u64(op, o0, o1);
                op += 4096;
            }
            if (comp) {
                const float xv = xnext;
                {
                    int nb = batch + NUM_CLUSTERS;
                    int nrow = (r < ROWS_ITER - 1) ? (row0 + r + 1)
                             : ((nb < NBATCH) ? nb * ROWS_ITER : row0);
                    xnext = x[(size_t)nrow * 512 + feat];
                }

                const float xs = xv * sc;
                // matvec with Chebyshev fused in (T computed, packed, consumed)
                ull acc0 = W2[0][0], acc1 = W2[0][1];   // T0 == 1
                {
                    ull tp = pack2(xs, xs);             // T1
                    acc0 = ffma2(tp, W2[1][0], acc0);
                    acc1 = ffma2(tp, W2[1][1], acc1);
                    const float x2 = xs + xs;
                    float tm2 = 1.0f, tm1 = xs;
                    #pragma unroll
                    for (int m = 2; m < 8; m++) {
                        const float T = fmaf(x2, tm1, -tm2);
                        tm2 = tm1; tm1 = T;
                        tp = pack2(T, T);
                        acc0 = ffma2(tp, W2[m][0], acc0);
                        acc1 = ffma2(tp, W2[m][1], acc1);
                    }
                }

                // silu via tanh: v = b*(1+tanh(b)), b = a/2
                float a0, a1, a2, a3;
                unpack2(acc0, a0, a1);
                unpack2(acc1, a2, a3);
                const float b0 = 0.5f * a0, b1 = 0.5f * a1;
                const float b2 = 0.5f * a2, b3 = 0.5f * a3;
                const float v0 = fmaf(tanhf_hw(b0), b0, b0);
                const float v1 = fmaf(tanhf_hw(b1), b1, b1);
                const float v2 = fmaf(tanhf_hw(b2), b2, b2);
                const float v3 = fmaf(tanhf_hw(b3), b3, b3);

                float sum = (v0 + v1) + (v2 + v3);
                float sq  = fmaf(v0, v0, fmaf(v1, v1, fmaf(v2, v2, v3 * v3)));

                *ap = make_float4(v0, v1, v2, v3);   // overwrite own slot (safe)

                // TRUNCATED in-loop reduction: 2 butterfly levels (groups of 4)
                sum += __shfl_xor_sync(0xffffffffu, sum, 1);
                sq  += __shfl_xor_sync(0xffffffffu, sq,  1);
                sum += __shfl_xor_sync(0xffffffffu, sum, 2);
                sq  += __shfl_xor_sync(0xffffffffu, sq,  2);
                if ((lane & 3) == 0)
                    ((float2*)(sm + SMEM_RED))[r * 256 + wid * 8 + (lane >> 2)] =
                        make_float2(sum, sq);
            }
            ap += TPB;
        }

        if (!comp) break;   // drain window flushed last epilogue; done
        __syncthreads();    // RED complete

        // ---- wide CTA-partial: warp w reduces row w (256 partials) ----
        if (wid < 8) {
            const ull* base = (const ull*)(sm + SMEM_RED) + wid * 256;
            ull v = base[lane];
            #pragma unroll
            for (int q = 1; q < 8; q++) v = fadd2(v, base[lane + q * 32]);
            float s0, q0;
            unpack2(v, s0, q0);
            #pragma unroll
            for (int o = 16; o > 0; o >>= 1) {
                s0 += __shfl_xor_sync(0xffffffffu, s0, o);
                q0 += __shfl_xor_sync(0xffffffffu, q0, o);
            }
            if (lane == 0) {
                const uint32_t laddr =
                    smem_u32((ull*)(sm + SMEM_PAR) + (p * 32 + wid * 4 + (int)h));
                const ull t = pack2(s0, q0);
                #pragma unroll
                for (uint32_t dst = 0; dst < 4; dst++)
                    st_remote_b64(mapa_rank(laddr, dst), t);
            }
        }
        cluster_sync();   // release our pushes / acquire peers' (PAR double-buffered)

        // ---- finish: 8 lane0s combine 4 rank totals, emit (rstd, off) ----
        if (wid < 8 && lane == 0) {
            const ull* pr = (const ull*)(sm + SMEM_PAR) + p * 32 + wid * 4;
            const ull t = fadd2(fadd2(pr[0], pr[1]), fadd2(pr[2], pr[3]));
            float s, q;
            unpack2(t, s, q);
            const float mean = s * invN;
            const float var  = fmaf(-mean, mean, q * invN);
            const float rstd = rsqrtf(var + 1e-5f);
            const float off  = -mean * rstd;
            ((ull*)(sm + SMEM_MRS))[wid] = pack2(rstd, rstd);
            ((ull*)(sm + SMEM_MRO))[wid] = pack2(off, off);
        }
        __syncthreads();    // MRS/MRO visible before next window's epilogue

        prev_row0 = row0;
    }
}

extern "C" void kernel_launch(void* const* d_in, const int* in_sizes, int n_in,
                              void* d_out, int out_size)
{
    const float* x     = (const float*)d_in[0];   // [4096, 512]
    const float* scale = (const float*)d_in[1];   // [512]
    const float* poly  = (const float*)d_in[2];   // [4, 512, 8]
    const float* kern  = (const float*)d_in[3];   // [4, 512, 8, 8]
    const float* gamma = (const float*)d_in[4];   // [16384]
    const float* beta  = (const float*)d_in[5];   // [16384]
    float* out = (float*)d_out;                   // [4096, 16384]

    (void)in_sizes; (void)n_in; (void)out_size;

    cudaFuncSetAttribute(cheb_fused_kernel,
                         cudaFuncAttributeMaxDynamicSharedMemorySize, SMEM_BYTES);

    cheb_fused_kernel<<<NBLK, TPB, SMEM_BYTES, 0>>>(x, scale, poly, kern, gamma, beta, out);
}